// round 16
// baseline (speedup 1.0000x reference)
#include <cuda_runtime.h>
#include <math.h>

// Problem constants
#define NBc   16
#define NAc   5
#define NKc   9
#define NCc   13
#define NHc   38
#define NWc   38
#define MAXTc 50
#define NPIX  (NHc*NWc)        // 1444
#define NANCH (NAc*NPIX)       // 7220
#define NTOTc (NBc*NANCH)      // 115520
#define CHPA  (2*NKc+1+NCc)    // 32
#define TROW  21

#define TPB   288                      // 9 warps
#define NWRP  (TPB/32)
#define BPB   ((NANCH + TPB - 1)/TPB)  // 26 blocks per batch
#define NBLK  (NBc*BPB)                // 416 blocks

#define SCX   (640.0f/38.0f)
#define SCY   (480.0f/38.0f)
#define DENOM9   57.50150489f
#define STHRESH  34.50090293f   // 0.6 * 9 * (e^2 - 1)
// ssum > STHRESH requires a corner with |dx|<=16.98 AND |dy|<=16.98 -> 17px margin
#define MARGIN   17.0f

__device__ float g_part[NBLK][2];
__device__ int   g_cnt = 0;

__device__ __forceinline__ float sigf(float x) { return 1.0f / (1.0f + __expf(-x)); }

__global__ void __launch_bounds__(TPB, 3)
k_main(const float* __restrict__ out,
       const float* __restrict__ tgt,
       const float* __restrict__ anc,
       const void*  __restrict__ epoch_ptr,
       float* __restrict__ d_out) {
    __shared__ float  s_t[MAXTc*TROW];                // staged target rows
    __shared__ int    s_nv;
    __shared__ int    s_key[MAXTc];
    __shared__ float  s_cls[MAXTc];
    __shared__ __align__(16) float4 s_bb[MAXTc];      // target corner bbox
    __shared__ __align__(16) float4 s_gq[MAXTc][5];   // corners (10 f2 slots)
    __shared__ __align__(16) float2 s_v[MAXTc*NKc];   // coord targets
    __shared__ float2 s_wred[NWRP];
    __shared__ bool   s_last;

    const int tid  = threadIdx.x;
    const int lane = tid & 31;
    const int wid  = tid >> 5;
    const int b    = blockIdx.x / BPB;
    const int cell = (blockIdx.x % BPB) * TPB + tid;
    const bool ok  = (cell < NANCH);
    const float* tgb = tgt + (size_t)b * (MAXTc*TROW);

    // ---- per-cell channel loads, issued early; fold into Px/Py + bbox ------
    int a = 0, h = 0, w = 0;
    const float* baseo = out;
    float Px[NKc], Py[NKc], confv = 0.0f;
    float pxmn = 1e30f, pxmx = -1e30f, pymn = 1e30f, pymx = -1e30f;
    if (ok) {
        a = cell / NPIX;
        int pix = cell % NPIX;
        h = pix / NWc; w = pix % NWc;
        baseo = out + ((size_t)(b * NAc + a) * CHPA) * NPIX + pix;
        float rc = baseo[(2*NKc) * NPIX];
        #pragma unroll
        for (int k = 0; k < NKc; ++k) {
            float xv = baseo[(2*k)   * NPIX];
            float yv = baseo[(2*k+1) * NPIX];
            if (k == 0) { xv = sigf(xv); yv = sigf(yv); }
            Px[k] = (xv + (float)w) * SCX;
            Py[k] = (yv + (float)h) * SCY;
            pxmn = fminf(pxmn, Px[k]);  pxmx = fmaxf(pxmx, Px[k]);
            pymn = fminf(pymn, Py[k]);  pymx = fmaxf(pymx, Py[k]);
        }
        confv = sigf(rc);
    }
    const float pxmnE = pxmn - MARGIN, pxmxE = pxmx + MARGIN;
    const float pymnE = pymn - MARGIN, pymxE = pymx + MARGIN;

    // ---- stage targets coalesced -------------------------------------------
    for (int i = tid; i < MAXTc*TROW; i += TPB)
        s_t[i] = tgb[i];
    __syncthreads();

    // ---- validity prefix via ballots (warp 0) ------------------------------
    if (wid == 0) {
        unsigned m0 = __ballot_sync(0xFFFFFFFFu, s_t[lane*TROW + 1] != 0.0f);
        unsigned m1 = __ballot_sync(0xFFFFFFFFu,
                          (lane < MAXTc - 32) && (s_t[(lane+32)*TROW + 1] != 0.0f));
        if (lane == 0) {
            int nv;
            if (~m0) nv = __ffs(~m0) - 1;
            else {
                unsigned inv = (~m1) & ((1u << (MAXTc - 32)) - 1u);
                nv = inv ? 32 + __ffs(inv) - 1 : MAXTc;
            }
            s_nv = nv;
        }
    }

    // ---- per-target meta (keys, corners, coord targets, bbox) --------------
    if (tid < MAXTc && s_t[tid*TROW + 1] != 0.0f) {
        const int t = tid;
        const float* tb = &s_t[t*TROW];

        float gw = tb[19] * (float)NWc;
        float gh = tb[20] * (float)NHc;
        float best = -1.0f; int bn = 0;
        #pragma unroll
        for (int aa = 0; aa < NAc; ++aa) {
            float aw = anc[2*aa], ah = anc[2*aa+1];
            float cw = fminf(gw, aw), ch = fminf(gh, ah);
            float iou = 0.0f;
            if (cw > 0.0f && ch > 0.0f) {
                float ca = cw * ch;
                iou = ca / (gw * gh + aw * ah - ca);
            }
            if (iou > best) { best = iou; bn = aa; }
        }
        int gi0 = (int)floorf(tb[1] * (float)NWc);
        int gj0 = (int)floorf(tb[2] * (float)NHc);
        s_key[t] = (bn << 12) | (gj0 << 6) | gi0;
        s_cls[t] = tb[0];

        float* gq = (float*)&s_gq[t][0];
        float xmn = 1e30f, xmx = -1e30f, ymn = 1e30f, ymx = -1e30f;
        #pragma unroll
        for (int k = 0; k < NKc; ++k) {
            float gx = tb[1 + 2*k] * 640.0f;
            float gy = tb[2 + 2*k] * 480.0f;
            gq[2*k]   = gx;
            gq[2*k+1] = gy;
            xmn = fminf(xmn, gx);  xmx = fmaxf(xmx, gx);
            ymn = fminf(ymn, gy);  ymx = fmaxf(ymx, gy);
            s_v[t*NKc + k] = make_float2(tb[1 + 2*k] * (float)NWc - (float)gi0,
                                         tb[2 + 2*k] * (float)NHc - (float)gj0);
        }
        s_bb[t] = make_float4(xmn, xmx, ymn, ymx);
        gq[18] = 1.0e9f;  gq[19] = 1.0e9f;   // sentinel 10th corner slot
    }
    __syncthreads();
    const int nv = s_nv;

    // ---- single scan: key match + bbox overlap gate (cheap) ----------------
    float baseLoss = 0.0f, confLoss = 0.0f;

    if (ok) {
        const int mykey = (a << 12) | (h << 6) | w;
        int m = -1;
        unsigned long long gatemask = 0ull;
        for (int t = 0; t < nv; ++t) {
            if (s_key[t] == mykey) m = t;              // predicated SEL
            float4 bb = s_bb[t];                       // one LDS.128
            bool ov = (bb.y >= pxmnE) & (bb.x <= pxmxE)
                    & (bb.w >= pymnE) & (bb.z <= pymxE);
            gatemask |= ov ? (1ull << t) : 0ull;       // predicated
        }

        if (m >= 0) {
            // matched (rare): coord + CE + obj-conf (tconf computed inline)
            #pragma unroll
            for (int k = 0; k < NKc; ++k) {
                float xv = baseo[(2*k)   * NPIX];
                float yv = baseo[(2*k+1) * NPIX];
                if (k == 0) { xv = sigf(xv); yv = sigf(yv); }
                float2 v = s_v[m*NKc + k];
                float dx = xv - v.x;
                float dy = yv - v.y;
                baseLoss += 0.5f * (dx*dx + dy*dy);
            }
            float mx = -1e30f;
            #pragma unroll
            for (int c = 0; c < NCc; ++c)
                mx = fmaxf(mx, baseo[(2*NKc + 1 + c) * NPIX]);
            float se = 0.0f;
            #pragma unroll
            for (int c = 0; c < NCc; ++c)
                se += __expf(baseo[(2*NKc + 1 + c) * NPIX] - mx);
            int lab = (int)s_cls[m];
            lab = lab < 0 ? 0 : (lab > NCc - 1 ? NCc - 1 : lab);
            baseLoss += __logf(se) + mx - baseo[(2*NKc + 1 + lab) * NPIX];

            // tconf at the pidx-shifted cell for this target
            int gi0 = mykey & 63, gj0 = (mykey >> 6) & 63;
            long long p = (long long)b * NANCH - NPIX + (long long)gj0 * NWc + gi0;
            const long long tot = NTOTc;
            p = ((p % tot) + tot) % tot;
            int b2  = (int)(p / NANCH);
            int rem = (int)(p % NANCH);
            int a2  = rem / NPIX;
            int px2 = rem % NPIX;
            int h2 = px2 / NWc, w2 = px2 % NWc;
            const float* bo2 = out + ((size_t)(b2 * NAc + a2) * CHPA) * NPIX + px2;
            const float* gq = (const float*)&s_gq[m][0];
            float s = 0.0f;
            #pragma unroll
            for (int k = 0; k < NKc; ++k) {
                float xv = bo2[(2*k)   * NPIX];
                float yv = bo2[(2*k+1) * NPIX];
                if (k == 0) { xv = sigf(xv); yv = sigf(yv); }
                float qx = (xv + (float)w2) * SCX;
                float qy = (yv + (float)h2) * SCY;
                float dx = gq[2*k]   - qx;
                float dy = gq[2*k+1] - qy;
                float d2 = fmaf(dx, dx, dy * dy);
                if (d2 < 6400.0f) s += __expf(2.0f - sqrtf(d2) * 0.025f) - 1.0f;
            }
            float dc = confv - s * (1.0f / DENOM9);
            confLoss = 2.5f * dc * dc;
        } else {
            // exact evaluation of gated (bbox-overlapping) targets — rare
            bool silent = false;
            while (gatemask && !silent) {
                int t = __ffsll(gatemask) - 1;
                gatemask &= gatemask - 1ull;
                const float2* gp = (const float2*)(s_gq + t);
                float ssum = 0.0f;
                #pragma unroll
                for (int k = 0; k < NKc; ++k) {
                    float dx = Px[k] - gp[k].x;
                    float dy = Py[k] - gp[k].y;
                    float d2 = fmaf(dx, dx, dy * dy);
                    if (d2 < 6400.0f)
                        ssum += __expf(2.0f - sqrtf(d2) * 0.025f) - 1.0f;
                }
                if (ssum > STHRESH) silent = true;
            }
            if (!silent) confLoss = 0.5f * confv * confv;
        }
    }

    // ---- block reduction ----------------------------------------------------
    float v0 = baseLoss, v1 = confLoss;
    #pragma unroll
    for (int o = 16; o > 0; o >>= 1) {
        v0 += __shfl_down_sync(0xFFFFFFFFu, v0, o);
        v1 += __shfl_down_sync(0xFFFFFFFFu, v1, o);
    }
    if (lane == 0) s_wred[wid] = make_float2(v0, v1);
    __syncthreads();
    if (tid == 0) {
        float rb = 0.0f, rc = 0.0f;
        #pragma unroll
        for (int j = 0; j < NWRP; ++j) { rb += s_wred[j].x; rc += s_wred[j].y; }
        g_part[blockIdx.x][0] = rb;
        g_part[blockIdx.x][1] = rc;
    }

    // ---- last-block-done final reduction ------------------------------------
    __threadfence();
    if (tid == 0) {
        int old = atomicAdd(&g_cnt, 1);
        s_last = (old == NBLK - 1);
    }
    __syncthreads();
    if (!s_last) return;

    float rb = 0.0f, rc = 0.0f;
    for (int idx = tid; idx < NBLK; idx += TPB) {
        rb += g_part[idx][0];
        rc += g_part[idx][1];
    }
    #pragma unroll
    for (int o = 16; o > 0; o >>= 1) {
        rb += __shfl_down_sync(0xFFFFFFFFu, rb, o);
        rc += __shfl_down_sync(0xFFFFFFFFu, rc, o);
    }
    if (lane == 0) s_wred[wid] = make_float2(rb, rc);
    __syncthreads();
    if (tid == 0) {
        float tb2 = 0.0f, tc2 = 0.0f;
        #pragma unroll
        for (int j = 0; j < NWRP; ++j) { tb2 += s_wred[j].x; tc2 += s_wred[j].y; }
        int ev = ((const int*)epoch_ptr)[0];
        if (ev > 1000000 || ev < -1000000) ev = (int)__int_as_float(ev);
        float total = tb2;
        if (ev > 15) total += tc2;
        d_out[0] = total;
        g_cnt = 0;   // reset for graph replay
    }
}

extern "C" void kernel_launch(void* const* d_in, const int* in_sizes, int n_in,
                              void* d_out, int out_size) {
    const float* out_t = (const float*)d_in[0];
    const float* tgt   = (const float*)d_in[1];
    const float* anc   = (const float*)d_in[2];
    const void*  epoch = d_in[3];
    k_main<<<NBLK, TPB>>>(out_t, tgt, anc, epoch, (float*)d_out);
}

// round 17
// speedup vs baseline: 1.2424x; 1.2424x over previous
#include <cuda_runtime.h>
#include <math.h>

// Problem constants
#define NBc   16
#define NAc   5
#define NKc   9
#define NCc   13
#define NHc   38
#define NWc   38
#define MAXTc 50
#define NPIX  (NHc*NWc)        // 1444
#define NANCH (NAc*NPIX)       // 7220
#define NTOTc (NBc*NANCH)      // 115520
#define CHPA  (2*NKc+1+NCc)    // 32
#define TROW  21

#define TPB   256
#define BPB   ((NANCH + TPB - 1)/TPB)  // 29 blocks per batch
#define NBLK  (NBc*BPB)                // 464 blocks (1 wave @4/SM)

#define SCX   (640.0f/38.0f)
#define SCY   (480.0f/38.0f)
#define DENOM9   57.50150489f
#define STHRESH  34.50090293f   // 0.6 * 9 * (e^2 - 1)
// ssum > STHRESH requires max corner term >= STHRESH/9 -> some d2 < 288.12
#define GATE2    290.0f

__device__ float g_part[NBLK][2];
__device__ int   g_cnt = 0;

__device__ __forceinline__ float sigf(float x) { return 1.0f / (1.0f + __expf(-x)); }

__global__ void __launch_bounds__(TPB, 4)
k_main(const float* __restrict__ out,
       const float* __restrict__ tgt,
       const float* __restrict__ anc,
       const void*  __restrict__ epoch_ptr,
       float* __restrict__ d_out) {
    __shared__ float  s_t[MAXTc*TROW];                // staged target rows
    __shared__ int    s_nv;
    __shared__ int    s_key[MAXTc];
    __shared__ float  s_cls[MAXTc];
    __shared__ __align__(16) float4 s_gq[MAXTc][5];   // corners (10 f2 slots)
    __shared__ __align__(16) float2 s_v[MAXTc*NKc];   // coord targets
    __shared__ float2 s_wred[TPB/32];
    __shared__ bool   s_last;

    const int tid  = threadIdx.x;
    const int lane = tid & 31;
    const int wid  = tid >> 5;
    const int b    = blockIdx.x / BPB;
    const int cell = (blockIdx.x % BPB) * TPB + tid;
    const bool ok  = (cell < NANCH);
    const float* tgb = tgt + (size_t)b * (MAXTc*TROW);

    // ---- per-cell channel loads: issue only, consume AFTER the barrier -----
    int a = 0, h = 0, w = 0;
    const float* baseo = out;
    float rx[NKc], ry[NKc], rconf = 0.0f;
    if (ok) {
        a = cell / NPIX;
        int pix = cell % NPIX;
        h = pix / NWc; w = pix % NWc;
        baseo = out + ((size_t)(b * NAc + a) * CHPA) * NPIX + pix;
        #pragma unroll
        for (int k = 0; k < NKc; ++k) {
            rx[k] = baseo[(2*k)   * NPIX];
            ry[k] = baseo[(2*k+1) * NPIX];
        }
        rconf = baseo[(2*NKc) * NPIX];
    }

    // ---- stage targets coalesced (overlaps with channel-load latency) ------
    for (int i = tid; i < MAXTc*TROW; i += TPB)
        s_t[i] = tgb[i];
    __syncthreads();

    // ---- validity prefix via ballots (warp 0) ------------------------------
    if (wid == 0) {
        unsigned m0 = __ballot_sync(0xFFFFFFFFu, s_t[lane*TROW + 1] != 0.0f);
        unsigned m1 = __ballot_sync(0xFFFFFFFFu,
                          (lane < MAXTc - 32) && (s_t[(lane+32)*TROW + 1] != 0.0f));
        if (lane == 0) {
            int nv;
            if (~m0) nv = __ffs(~m0) - 1;
            else {
                unsigned inv = (~m1) & ((1u << (MAXTc - 32)) - 1u);
                nv = inv ? 32 + __ffs(inv) - 1 : MAXTc;
            }
            s_nv = nv;
        }
    }

    // ---- per-target meta (no tconf; cheap) ---------------------------------
    if (tid < MAXTc && s_t[tid*TROW + 1] != 0.0f) {
        const int t = tid;
        const float* tb = &s_t[t*TROW];

        float gw = tb[19] * (float)NWc;
        float gh = tb[20] * (float)NHc;
        float best = -1.0f; int bn = 0;
        #pragma unroll
        for (int aa = 0; aa < NAc; ++aa) {
            float aw = anc[2*aa], ah = anc[2*aa+1];
            float cw = fminf(gw, aw), ch = fminf(gh, ah);
            float iou = 0.0f;
            if (cw > 0.0f && ch > 0.0f) {
                float ca = cw * ch;
                iou = ca / (gw * gh + aw * ah - ca);
            }
            if (iou > best) { best = iou; bn = aa; }
        }
        int gi0 = (int)floorf(tb[1] * (float)NWc);
        int gj0 = (int)floorf(tb[2] * (float)NHc);
        s_key[t] = (bn << 12) | (gj0 << 6) | gi0;
        s_cls[t] = tb[0];

        float* gq = (float*)&s_gq[t][0];
        #pragma unroll
        for (int k = 0; k < NKc; ++k) {
            float gx = tb[1 + 2*k], gy = tb[2 + 2*k];
            gq[2*k]   = gx * 640.0f;
            gq[2*k+1] = gy * 480.0f;
            s_v[t*NKc + k] = make_float2(gx * (float)NWc - (float)gi0,
                                         gy * (float)NHc - (float)gj0);
        }
        gq[18] = 1.0e9f;  gq[19] = 1.0e9f;   // sentinel 10th corner slot
    }
    __syncthreads();
    const int nv = s_nv;

    // ---- NOW consume channel loads (fully landed) --------------------------
    float Px[NKc], Py[NKc], confv = 0.0f;
    if (ok) {
        rx[0] = sigf(rx[0]);  ry[0] = sigf(ry[0]);
        #pragma unroll
        for (int k = 0; k < NKc; ++k) {
            Px[k] = (rx[k] + (float)w) * SCX;
            Py[k] = (ry[k] + (float)h) * SCY;
        }
        confv = sigf(rconf);
    }

    // ---- per-cell loss ------------------------------------------------------
    float baseLoss = 0.0f, confLoss = 0.0f;

    if (ok) {
        const int mykey = (a << 12) | (h << 6) | w;
        int m = -1;
        unsigned long long gatemask = 0ull;

        // branch-free scan: key match + dmin gate recorded, exp deferred
        for (int t = 0; t < nv; ++t) {
            if (s_key[t] == mykey) m = t;              // predicated SEL
            float4 q0 = s_gq[t][0];
            float4 q1 = s_gq[t][1];
            float4 q2 = s_gq[t][2];
            float4 q3 = s_gq[t][3];
            float4 q4 = s_gq[t][4];
            float d2[NKc];
            { float dx = Px[0]-q0.x, dy = Py[0]-q0.y; d2[0] = fmaf(dx,dx,dy*dy); }
            { float dx = Px[1]-q0.z, dy = Py[1]-q0.w; d2[1] = fmaf(dx,dx,dy*dy); }
            { float dx = Px[2]-q1.x, dy = Py[2]-q1.y; d2[2] = fmaf(dx,dx,dy*dy); }
            { float dx = Px[3]-q1.z, dy = Py[3]-q1.w; d2[3] = fmaf(dx,dx,dy*dy); }
            { float dx = Px[4]-q2.x, dy = Py[4]-q2.y; d2[4] = fmaf(dx,dx,dy*dy); }
            { float dx = Px[5]-q2.z, dy = Py[5]-q2.w; d2[5] = fmaf(dx,dx,dy*dy); }
            { float dx = Px[6]-q3.x, dy = Py[6]-q3.y; d2[6] = fmaf(dx,dx,dy*dy); }
            { float dx = Px[7]-q3.z, dy = Py[7]-q3.w; d2[7] = fmaf(dx,dx,dy*dy); }
            { float dx = Px[8]-q4.x, dy = Py[8]-q4.y; d2[8] = fmaf(dx,dx,dy*dy); }
            float m01 = fminf(d2[0], d2[1]), m23 = fminf(d2[2], d2[3]);
            float m45 = fminf(d2[4], d2[5]), m67 = fminf(d2[6], d2[7]);
            float dmin = fminf(fminf(fminf(m01, m23), fminf(m45, m67)), d2[8]);
            gatemask |= (dmin < GATE2) ? (1ull << t) : 0ull;   // predicated
        }

        if (m >= 0) {
            // matched (rare): coord + CE + obj-conf (tconf computed inline)
            #pragma unroll
            for (int k = 0; k < NKc; ++k) {
                float2 v = s_v[m*NKc + k];
                float dx = rx[k] - v.x;
                float dy = ry[k] - v.y;
                baseLoss += 0.5f * (dx*dx + dy*dy);
            }
            float mx = -1e30f;
            #pragma unroll
            for (int c = 0; c < NCc; ++c)
                mx = fmaxf(mx, baseo[(2*NKc + 1 + c) * NPIX]);
            float se = 0.0f;
            #pragma unroll
            for (int c = 0; c < NCc; ++c)
                se += __expf(baseo[(2*NKc + 1 + c) * NPIX] - mx);
            int lab = (int)s_cls[m];
            lab = lab < 0 ? 0 : (lab > NCc - 1 ? NCc - 1 : lab);
            baseLoss += __logf(se) + mx - baseo[(2*NKc + 1 + lab) * NPIX];

            // tconf at the pidx-shifted cell for this target
            int gi0 = mykey & 63, gj0 = (mykey >> 6) & 63;
            long long p = (long long)b * NANCH - NPIX + (long long)gj0 * NWc + gi0;
            const long long tot = NTOTc;
            p = ((p % tot) + tot) % tot;
            int b2  = (int)(p / NANCH);
            int rem = (int)(p % NANCH);
            int a2  = rem / NPIX;
            int px2 = rem % NPIX;
            int h2 = px2 / NWc, w2 = px2 % NWc;
            const float* bo2 = out + ((size_t)(b2 * NAc + a2) * CHPA) * NPIX + px2;
            const float* gq = (const float*)&s_gq[m][0];
            float s = 0.0f;
            #pragma unroll
            for (int k = 0; k < NKc; ++k) {
                float xv = bo2[(2*k)   * NPIX];
                float yv = bo2[(2*k+1) * NPIX];
                if (k == 0) { xv = sigf(xv); yv = sigf(yv); }
                float qx = (xv + (float)w2) * SCX;
                float qy = (yv + (float)h2) * SCY;
                float dx = gq[2*k]   - qx;
                float dy = gq[2*k+1] - qy;
                float d2 = fmaf(dx, dx, dy * dy);
                if (d2 < 6400.0f) s += __expf(2.0f - sqrtf(d2) * 0.025f) - 1.0f;
            }
            float dc = confv - s * (1.0f / DENOM9);
            confLoss = 2.5f * dc * dc;
        } else {
            // deferred exact evaluation of gated targets (rare, ~2-3%)
            bool silent = false;
            while (gatemask && !silent) {
                int t = __ffsll(gatemask) - 1;
                gatemask &= gatemask - 1ull;
                const float2* gp = (const float2*)(s_gq + t);
                float ssum = 0.0f;
                #pragma unroll
                for (int k = 0; k < NKc; ++k) {
                    float dx = Px[k] - gp[k].x;
                    float dy = Py[k] - gp[k].y;
                    float d2 = fmaf(dx, dx, dy * dy);
                    if (d2 < 6400.0f)
                        ssum += __expf(2.0f - sqrtf(d2) * 0.025f) - 1.0f;
                }
                if (ssum > STHRESH) silent = true;
            }
            if (!silent) confLoss = 0.5f * confv * confv;
        }
    }

    // ---- block reduction ----------------------------------------------------
    float v0 = baseLoss, v1 = confLoss;
    #pragma unroll
    for (int o = 16; o > 0; o >>= 1) {
        v0 += __shfl_down_sync(0xFFFFFFFFu, v0, o);
        v1 += __shfl_down_sync(0xFFFFFFFFu, v1, o);
    }
    if (lane == 0) s_wred[wid] = make_float2(v0, v1);
    __syncthreads();
    if (tid == 0) {
        float rb = 0.0f, rc = 0.0f;
        #pragma unroll
        for (int j = 0; j < TPB/32; ++j) { rb += s_wred[j].x; rc += s_wred[j].y; }
        g_part[blockIdx.x][0] = rb;
        g_part[blockIdx.x][1] = rc;
    }

    // ---- last-block-done final reduction ------------------------------------
    __threadfence();
    if (tid == 0) {
        int old = atomicAdd(&g_cnt, 1);
        s_last = (old == NBLK - 1);
    }
    __syncthreads();
    if (!s_last) return;

    float rb = 0.0f, rc = 0.0f;
    for (int idx = tid; idx < NBLK; idx += TPB) {
        rb += g_part[idx][0];
        rc += g_part[idx][1];
    }
    #pragma unroll
    for (int o = 16; o > 0; o >>= 1) {
        rb += __shfl_down_sync(0xFFFFFFFFu, rb, o);
        rc += __shfl_down_sync(0xFFFFFFFFu, rc, o);
    }
    if (lane == 0) s_wred[wid] = make_float2(rb, rc);
    __syncthreads();
    if (tid == 0) {
        float tb2 = 0.0f, tc2 = 0.0f;
        #pragma unroll
        for (int j = 0; j < TPB/32; ++j) { tb2 += s_wred[j].x; tc2 += s_wred[j].y; }
        int ev = ((const int*)epoch_ptr)[0];
        if (ev > 1000000 || ev < -1000000) ev = (int)__int_as_float(ev);
        float total = tb2;
        if (ev > 15) total += tc2;
        d_out[0] = total;
        g_cnt = 0;   // reset for graph replay
    }
}

extern "C" void kernel_launch(void* const* d_in, const int* in_sizes, int n_in,
                              void* d_out, int out_size) {
    const float* out_t = (const float*)d_in[0];
    const float* tgt   = (const float*)d_in[1];
    const float* anc   = (const float*)d_in[2];
    const void*  epoch = d_in[3];
    k_main<<<NBLK, TPB>>>(out_t, tgt, anc, epoch, (float*)d_out);
}